// round 3
// baseline (speedup 1.0000x reference)
#include <cuda_runtime.h>
#include <cuda_bf16.h>
#include <cstdint>

// ============================================================================
// Problem constants
// ============================================================================
static constexpr int T_TOK = 16384;        // B*S
static constexpr int HID   = 2048;
static constexpr int KVD   = 512;
static constexpr int TILE_M = 128;
static constexpr int TILE_N = 256;
static constexpr int KC     = 64;          // K elements per chunk (one 128B row)
static constexpr int NIT    = HID / KC;    // 32 chunks (3 combos folded per chunk)
static constexpr int A_TILE_B = TILE_M * 128;   // 16 KB
static constexpr int B_TILE_B = TILE_N * 128;   // 32 KB
static constexpr int STAGE_B  = 2 * A_TILE_B + 2 * B_TILE_B;  // 96 KB (Ah,Al,Bh,Bl)
static constexpr uint32_t SMEM_DYN = 2 * STAGE_B;             // 192 KB

// ============================================================================
// Scratch (static __device__ arrays — no runtime allocation)
// ============================================================================
__device__ __nv_bfloat16 g_Xh[(size_t)T_TOK * HID];
__device__ __nv_bfloat16 g_Xl[(size_t)T_TOK * HID];
__device__ __nv_bfloat16 g_Wqh[(size_t)HID * HID];
__device__ __nv_bfloat16 g_Wql[(size_t)HID * HID];
__device__ __nv_bfloat16 g_Wkh[(size_t)KVD * HID];
__device__ __nv_bfloat16 g_Wkl[(size_t)KVD * HID];
__device__ __nv_bfloat16 g_Wvh[(size_t)KVD * HID];
__device__ __nv_bfloat16 g_Wvl[(size_t)KVD * HID];
__device__ __nv_bfloat16 g_Woh[(size_t)HID * HID];
__device__ __nv_bfloat16 g_Wol[(size_t)HID * HID];
__device__ float g_Q[(size_t)T_TOK * HID];
__device__ float g_K[(size_t)T_TOK * KVD];
__device__ float g_V[(size_t)T_TOK * KVD];
__device__ __nv_bfloat16 g_Ah[(size_t)T_TOK * HID];
__device__ __nv_bfloat16 g_Al[(size_t)T_TOK * HID];

// ============================================================================
// Small helpers
// ============================================================================
__device__ __forceinline__ uint32_t smem_u32(const void* p) {
    uint32_t a;
    asm("{ .reg .u64 t; cvta.to.shared.u64 t, %1; cvt.u32.u64 %0, t; }" : "=r"(a) : "l"(p));
    return a;
}

__device__ __forceinline__ void ldsm4(uint32_t* r, uint32_t addr) {
    asm volatile("ldmatrix.sync.aligned.m8n8.x4.shared.b16 {%0,%1,%2,%3}, [%4];"
                 : "=r"(r[0]), "=r"(r[1]), "=r"(r[2]), "=r"(r[3]) : "r"(addr));
}

__device__ __forceinline__ void mma16816(float* c, const uint32_t* a, const uint32_t* b) {
    asm volatile("mma.sync.aligned.m16n8k16.row.col.f32.bf16.bf16.f32 "
                 "{%0,%1,%2,%3}, {%4,%5,%6,%7}, {%8,%9}, {%0,%1,%2,%3};"
                 : "+f"(c[0]), "+f"(c[1]), "+f"(c[2]), "+f"(c[3])
                 : "r"(a[0]), "r"(a[1]), "r"(a[2]), "r"(a[3]), "r"(b[0]), "r"(b[1]));
}

// ============================================================================
// fp32 -> (bf16 hi, bf16 lo) split. dsel: 0=X, 1=Wq, 2=Wk, 3=Wv, 4=Wo
// ============================================================================
__global__ void __launch_bounds__(256)
split_kernel(const float* __restrict__ s, int dsel, int n4) {
    __nv_bfloat162* hi;
    __nv_bfloat162* lo;
    switch (dsel) {
        case 0:  hi = (__nv_bfloat162*)g_Xh;  lo = (__nv_bfloat162*)g_Xl;  break;
        case 1:  hi = (__nv_bfloat162*)g_Wqh; lo = (__nv_bfloat162*)g_Wql; break;
        case 2:  hi = (__nv_bfloat162*)g_Wkh; lo = (__nv_bfloat162*)g_Wkl; break;
        case 3:  hi = (__nv_bfloat162*)g_Wvh; lo = (__nv_bfloat162*)g_Wvl; break;
        default: hi = (__nv_bfloat162*)g_Woh; lo = (__nv_bfloat162*)g_Wol; break;
    }
    int i = blockIdx.x * blockDim.x + threadIdx.x;
    if (i >= n4) return;
    float4 v = reinterpret_cast<const float4*>(s)[i];
    __nv_bfloat16 hx = __float2bfloat16(v.x);
    __nv_bfloat16 hy = __float2bfloat16(v.y);
    __nv_bfloat16 hz = __float2bfloat16(v.z);
    __nv_bfloat16 hw = __float2bfloat16(v.w);
    hi[2 * i]     = __halves2bfloat162(hx, hy);
    hi[2 * i + 1] = __halves2bfloat162(hz, hw);
    lo[2 * i]     = __halves2bfloat162(__float2bfloat16(v.x - __bfloat162float(hx)),
                                       __float2bfloat16(v.y - __bfloat162float(hy)));
    lo[2 * i + 1] = __halves2bfloat162(__float2bfloat16(v.z - __bfloat162float(hz)),
                                       __float2bfloat16(v.w - __bfloat162float(hw)));
}

// ============================================================================
// GEMM: C = (Ah+Al) @ (Bh+Bl)^T + bias  (ll term dropped, ~1e-8 rel)
//   A row-major [M, 2048], B row-major [N, 2048], C fp32 [M, ldc].
//   CTA 128x256, 8 warps (2m x 4n), warp tile 64x64, K-chunk 64,
//   2-stage cp.async double buffer, folded 3-combo mainloop.
// SW128 swizzle on 128B rows: dst16 = c16 ^ (row & 7).
// ============================================================================
__device__ __forceinline__ void load_stage(
    uint32_t sbase, int chunk, int m0, int n0,
    const __nv_bfloat16* __restrict__ Ah, const __nv_bfloat16* __restrict__ Al,
    const __nv_bfloat16* __restrict__ Bh, const __nv_bfloat16* __restrict__ Bl, int tid)
{
    int kk = chunk * KC;
    // A tiles: 128 rows x 8 c16 = 1024 quads each -> 4/thread
#pragma unroll
    for (int i = 0; i < 4; ++i) {
        int q = tid + (i << 8);
        int row = q >> 3, c16 = q & 7;
        uint32_t off = (uint32_t)((row << 7) | ((c16 ^ (row & 7)) << 4));
        const void* srcH = Ah + (size_t)(m0 + row) * HID + kk + (c16 << 3);
        const void* srcL = Al + (size_t)(m0 + row) * HID + kk + (c16 << 3);
        asm volatile("cp.async.cg.shared.global [%0], [%1], 16;"
                     :: "r"(sbase + off), "l"(srcH) : "memory");
        asm volatile("cp.async.cg.shared.global [%0], [%1], 16;"
                     :: "r"(sbase + A_TILE_B + off), "l"(srcL) : "memory");
    }
    // B tiles: 256 rows x 8 c16 = 2048 quads each -> 8/thread
#pragma unroll
    for (int i = 0; i < 8; ++i) {
        int q = tid + (i << 8);
        int row = q >> 3, c16 = q & 7;
        uint32_t off = (uint32_t)((row << 7) | ((c16 ^ (row & 7)) << 4));
        const void* srcH = Bh + (size_t)(n0 + row) * HID + kk + (c16 << 3);
        const void* srcL = Bl + (size_t)(n0 + row) * HID + kk + (c16 << 3);
        asm volatile("cp.async.cg.shared.global [%0], [%1], 16;"
                     :: "r"(sbase + 2 * A_TILE_B + off), "l"(srcH) : "memory");
        asm volatile("cp.async.cg.shared.global [%0], [%1], 16;"
                     :: "r"(sbase + 2 * A_TILE_B + B_TILE_B + off), "l"(srcL) : "memory");
    }
}

__global__ void __launch_bounds__(256, 1)
gemm3_kernel(int asel, int bsel, const float* __restrict__ bias,
             float* __restrict__ Cout, int csel, int ldc)
{
    const __nv_bfloat16* Ah = (asel == 0) ? g_Xh : g_Ah;
    const __nv_bfloat16* Al = (asel == 0) ? g_Xl : g_Al;
    const __nv_bfloat16* Bh;
    const __nv_bfloat16* Bl;
    switch (bsel) {
        case 0:  Bh = g_Wqh; Bl = g_Wql; break;
        case 1:  Bh = g_Wkh; Bl = g_Wkl; break;
        case 2:  Bh = g_Wvh; Bl = g_Wvl; break;
        default: Bh = g_Woh; Bl = g_Wol; break;
    }
    float* C;
    switch (csel) {
        case 0:  C = g_Q;  break;
        case 1:  C = g_K;  break;
        case 2:  C = g_V;  break;
        default: C = Cout; break;
    }

    extern __shared__ char smem_raw[];
    uint32_t sb = smem_u32(smem_raw);
    int tid  = threadIdx.x;
    int wid  = tid >> 5;
    int lane = tid & 31;
    int n0 = blockIdx.x * TILE_N;
    int m0 = blockIdx.y * TILE_M;
    int warpM = (wid & 1) * 64;    // warp m offset within CTA
    int warpN = (wid >> 1) * 64;   // warp n offset within CTA

    // Per-thread ldmatrix addressing: threads 0-15 -> rows 0-15 (k-half 0),
    // threads 16-31 -> rows 0-15 (k-half 1).
    int row16 = lane & 15;
    int half  = lane >> 4;
    int swr   = row16 & 7;

    float acc[4][8][4];
#pragma unroll
    for (int a = 0; a < 4; ++a)
#pragma unroll
        for (int b = 0; b < 8; ++b)
#pragma unroll
            for (int k = 0; k < 4; ++k) acc[a][b][k] = 0.f;

    // Prologue
    load_stage(sb, 0, m0, n0, Ah, Al, Bh, Bl, tid);
    asm volatile("cp.async.commit_group;" ::: "memory");

    for (int c = 0; c < NIT; ++c) {
        uint32_t cur = sb + (uint32_t)(c & 1) * STAGE_B;
        if (c + 1 < NIT) {
            load_stage(sb + (uint32_t)((c + 1) & 1) * STAGE_B, c + 1, m0, n0,
                       Ah, Al, Bh, Bl, tid);
            asm volatile("cp.async.commit_group;" ::: "memory");
            asm volatile("cp.async.wait_group 1;" ::: "memory");
        } else {
            asm volatile("cp.async.wait_group 0;" ::: "memory");
        }
        __syncthreads();

        uint32_t aH = cur;
        uint32_t aL = cur + A_TILE_B;
        uint32_t bH = cur + 2 * A_TILE_B;
        uint32_t bL = cur + 2 * A_TILE_B + B_TILE_B;

#pragma unroll
        for (int ks = 0; ks < 4; ++ks) {   // four k16 steps per 64-chunk
            uint32_t csel16 = (uint32_t)(((2 * ks + half) ^ swr) << 4);
            uint32_t ah[4][4], bh2[8][2], bl2[8][2], al[4][4];
            // Ah frags (4 m16 tiles)
#pragma unroll
            for (int mt = 0; mt < 4; ++mt) {
                uint32_t r = (uint32_t)((warpM + mt * 16 + row16) << 7);
                ldsm4(ah[mt], aH + r + csel16);
            }
            // Bh frags (4 n16 tiles -> 8 n8 frags)
#pragma unroll
            for (int nt = 0; nt < 4; ++nt) {
                uint32_t r = (uint32_t)((warpN + nt * 16 + row16) << 7);
                uint32_t t[4];
                ldsm4(t, bH + r + csel16);
                bh2[2 * nt][0] = t[0]; bh2[2 * nt][1] = t[2];
                bh2[2 * nt + 1][0] = t[1]; bh2[2 * nt + 1][1] = t[3];
            }
            // hh
#pragma unroll
            for (int mt = 0; mt < 4; ++mt)
#pragma unroll
                for (int j = 0; j < 8; ++j) mma16816(acc[mt][j], ah[mt], bh2[j]);
            // Bl frags
#pragma unroll
            for (int nt = 0; nt < 4; ++nt) {
                uint32_t r = (uint32_t)((warpN + nt * 16 + row16) << 7);
                uint32_t t[4];
                ldsm4(t, bL + r + csel16);
                bl2[2 * nt][0] = t[0]; bl2[2 * nt][1] = t[2];
                bl2[2 * nt + 1][0] = t[1]; bl2[2 * nt + 1][1] = t[3];
            }
            // hl
#pragma unroll
            for (int mt = 0; mt < 4; ++mt)
#pragma unroll
                for (int j = 0; j < 8; ++j) mma16816(acc[mt][j], ah[mt], bl2[j]);
            // Al frags
#pragma unroll
            for (int mt = 0; mt < 4; ++mt) {
                uint32_t r = (uint32_t)((warpM + mt * 16 + row16) << 7);
                ldsm4(al[mt], aL + r + csel16);
            }
            // lh
#pragma unroll
            for (int mt = 0; mt < 4; ++mt)
#pragma unroll
                for (int j = 0; j < 8; ++j) mma16816(acc[mt][j], al[mt], bh2[j]);
        }
        __syncthreads();
    }

    // Epilogue: c-frag (r, 2c) layout; add bias, store fp32.
    int rbase = m0 + warpM + (lane >> 2);
    int cbase = n0 + warpN + (lane & 3) * 2;
#pragma unroll
    for (int mt = 0; mt < 4; ++mt) {
#pragma unroll
        for (int j = 0; j < 8; ++j) {
            int col = cbase + j * 8;
            float b0 = bias[col], b1 = bias[col + 1];
            int r0 = rbase + mt * 16;
            float2 v0 = make_float2(acc[mt][j][0] + b0, acc[mt][j][1] + b1);
            float2 v1 = make_float2(acc[mt][j][2] + b0, acc[mt][j][3] + b1);
            *reinterpret_cast<float2*>(C + (size_t)r0 * ldc + col) = v0;
            *reinterpret_cast<float2*>(C + (size_t)(r0 + 8) * ldc + col) = v1;
        }
    }
}

// ============================================================================
// Per-token GQA mixing. One warp per token; lane owns 4 head-dims (float4).
// Writes bf16 hi/lo splits for the O projection.
// ============================================================================
__global__ void __launch_bounds__(128)
attn_kernel()
{
    __nv_bfloat162* Ah = (__nv_bfloat162*)g_Ah;
    __nv_bfloat162* Al = (__nv_bfloat162*)g_Al;
    int warp = threadIdx.x >> 5;
    int lane = threadIdx.x & 31;
    int t = blockIdx.x * 4 + warp;
    const float4* kp = reinterpret_cast<const float4*>(g_K + (size_t)t * KVD);
    const float4* vp = reinterpret_cast<const float4*>(g_V + (size_t)t * KVD);
    float4 kv[4], vv[4];
#pragma unroll
    for (int j = 0; j < 4; ++j) {
        kv[j] = kp[j * 32 + lane];
        vv[j] = vp[j * 32 + lane];
    }
    const float4* qp = reinterpret_cast<const float4*>(g_Q + (size_t)t * HID);
    const float scale = 0.08838834764831845f;   // 1/sqrt(128)
#pragma unroll 4
    for (int h = 0; h < 16; ++h) {
        float4 q = qp[h * 32 + lane];
        float s[4];
#pragma unroll
        for (int j = 0; j < 4; ++j)
            s[j] = q.x * kv[j].x + q.y * kv[j].y + q.z * kv[j].z + q.w * kv[j].w;
#pragma unroll
        for (int off = 16; off > 0; off >>= 1) {
#pragma unroll
            for (int j = 0; j < 4; ++j)
                s[j] += __shfl_xor_sync(0xffffffffu, s[j], off);
        }
#pragma unroll
        for (int j = 0; j < 4; ++j) s[j] *= scale;
        float m = fmaxf(fmaxf(s[0], s[1]), fmaxf(s[2], s[3]));
        float e0 = __expf(s[0] - m), e1 = __expf(s[1] - m);
        float e2 = __expf(s[2] - m), e3 = __expf(s[3] - m);
        float inv = 1.0f / (e0 + e1 + e2 + e3);
        float w0 = e0 * inv, w1 = e1 * inv, w2 = e2 * inv, w3 = e3 * inv;
        float4 o;
        o.x = w0 * vv[0].x + w1 * vv[1].x + w2 * vv[2].x + w3 * vv[3].x;
        o.y = w0 * vv[0].y + w1 * vv[1].y + w2 * vv[2].y + w3 * vv[3].y;
        o.z = w0 * vv[0].z + w1 * vv[1].z + w2 * vv[2].z + w3 * vv[3].z;
        o.w = w0 * vv[0].w + w1 * vv[1].w + w2 * vv[2].w + w3 * vv[3].w;
        size_t b2 = (size_t)t * (HID / 2) + h * 64 + lane * 2;
        __nv_bfloat16 hx = __float2bfloat16(o.x);
        __nv_bfloat16 hy = __float2bfloat16(o.y);
        __nv_bfloat16 hz = __float2bfloat16(o.z);
        __nv_bfloat16 hw = __float2bfloat16(o.w);
        Ah[b2]     = __halves2bfloat162(hx, hy);
        Ah[b2 + 1] = __halves2bfloat162(hz, hw);
        Al[b2]     = __halves2bfloat162(__float2bfloat16(o.x - __bfloat162float(hx)),
                                        __float2bfloat16(o.y - __bfloat162float(hy)));
        Al[b2 + 1] = __halves2bfloat162(__float2bfloat16(o.z - __bfloat162float(hz)),
                                        __float2bfloat16(o.w - __bfloat162float(hw)));
    }
}

// ============================================================================
// Host launcher
// ============================================================================
extern "C" void kernel_launch(void* const* d_in, const int* in_sizes, int n_in,
                              void* d_out, int out_size) {
    (void)in_sizes; (void)n_in; (void)out_size;
    const float* x  = (const float*)d_in[0];
    const float* bq = (const float*)d_in[2];
    const float* bk = (const float*)d_in[4];
    const float* bv = (const float*)d_in[6];
    const float* bo = (const float*)d_in[8];
    float* out = (float*)d_out;

    cudaFuncSetAttribute(gemm3_kernel, cudaFuncAttributeMaxDynamicSharedMemorySize,
                         (int)SMEM_DYN);

    // fp32 -> bf16 hi/lo splits
    {
        int n4 = T_TOK * HID / 4;
        split_kernel<<<(n4 + 255) / 256, 256>>>(x, 0, n4);
    }
    {
        int n4 = HID * HID / 4;
        split_kernel<<<(n4 + 255) / 256, 256>>>((const float*)d_in[1], 1, n4);
        split_kernel<<<(n4 + 255) / 256, 256>>>((const float*)d_in[7], 4, n4);
    }
    {
        int n4 = KVD * HID / 4;
        split_kernel<<<(n4 + 255) / 256, 256>>>((const float*)d_in[3], 2, n4);
        split_kernel<<<(n4 + 255) / 256, 256>>>((const float*)d_in[5], 3, n4);
    }

    // Q / K / V projections
    gemm3_kernel<<<dim3(HID / TILE_N, T_TOK / TILE_M), 256, SMEM_DYN>>>(
        0, 0, bq, nullptr, 0, HID);
    gemm3_kernel<<<dim3(KVD / TILE_N, T_TOK / TILE_M), 256, SMEM_DYN>>>(
        0, 1, bk, nullptr, 1, KVD);
    gemm3_kernel<<<dim3(KVD / TILE_N, T_TOK / TILE_M), 256, SMEM_DYN>>>(
        0, 2, bv, nullptr, 2, KVD);

    // Per-token GQA mixing -> bf16 splits for O projection
    attn_kernel<<<T_TOK / 4, 128>>>();

    // O projection straight into d_out
    gemm3_kernel<<<dim3(HID / TILE_N, T_TOK / TILE_M), 256, SMEM_DYN>>>(
        1, 3, bo, out, 3, HID);
}